// round 15
// baseline (speedup 1.0000x reference)
#include <cuda_runtime.h>
#include <cuda_fp16.h>
#include <math.h>
#include <stdint.h>

#define Bb 8
#define Tt 2048
#define Cc 768
#define Hh 64
#define NROW (Bb*Tt)   // 16384

// Pre-fragmented operands in GMEM. fp16 arrays are declared as float arrays
// (half element count) to guarantee 16B alignment for float4 access.
__device__ float g_wf[3*Cc*Hh/2];    // W fp16 B-frag k16 per (which, kchunk64)
__device__ float g_qf[NROW*Hh/2];    // Q*scale fp16 A-frag k16, per (b,qblk128)
__device__ float g_kf[NROW*Hh/2];    // K fp16 B-frag k16 (n=token,k=h), per (b,ktile64)
__device__ float g_vf[NROW*Hh/2];    // V fp16 B-frag k16 (n=h,k=token), per (b,ktile64)
__device__ float g_op[2*NROW*Hh];    // partial O per key-half
__device__ float g_ls[2*NROW];       // partial row sums per key-half
__device__ unsigned g_cnt[Bb*16];    // finalize tickets per (b,qblk); self-resetting

// ---------------------------------------------------------------------------
__device__ __forceinline__ uint32_t smem_u32(const void* p){
    uint32_t a;
    asm("{ .reg .u64 t; cvta.to.shared.u64 t, %1; cvt.u32.u64 %0, t; }"
        : "=r"(a) : "l"(p));
    return a;
}
// pack two f32 -> f16x2 (lo = first arg in low half, hi = second in high half)
__device__ __forceinline__ uint32_t pk(float lo, float hi){
    __half2 h = __floats2half2_rn(lo, hi);
    return *(uint32_t*)&h;
}
__device__ __forceinline__ void mma16(float d[4], uint32_t a0, uint32_t a1,
                                      uint32_t a2, uint32_t a3, uint2 b){
    asm volatile(
      "mma.sync.aligned.m16n8k16.row.col.f32.f16.f16.f32 "
      "{%0,%1,%2,%3}, {%4,%5,%6,%7}, {%8,%9}, {%0,%1,%2,%3};"
      : "+f"(d[0]), "+f"(d[1]), "+f"(d[2]), "+f"(d[3])
      : "r"(a0), "r"(a1), "r"(a2), "r"(a3), "r"(b.x), "r"(b.y));
}
__device__ __forceinline__ float exp2_mufu(float x){
    float r; asm("ex2.approx.ftz.f32 %0, %1;" : "=f"(r) : "f"(x)); return r;
}
#define CP16(dst, src) \
    asm volatile("cp.async.cg.shared.global [%0], [%1], 16;" \
                 :: "r"(dst), "l"(src) : "memory")
#define CP_COMMIT() asm volatile("cp.async.commit_group;" ::: "memory")
#define CP_WAIT(n)  asm volatile("cp.async.wait_group %0;" :: "n"(n) : "memory")

// ---------------------------------------------------------------------------
// prep_w: W[768,64] -> fp16 B-frag k16 (n=h, k=c). grid 36. order 0=K,1=Q,2=V
// ---------------------------------------------------------------------------
__global__ void __launch_bounds__(256) prep_w(
    const float* __restrict__ Wk, const float* __restrict__ Wq,
    const float* __restrict__ Wv)
{
    const int which = blockIdx.x / 12, ch = blockIdx.x % 12;
    const float* __restrict__ W = (which==0)?Wk:((which==1)?Wq:Wv);
    const int t = threadIdx.x, lane = t & 31, j = t >> 5;
    const int g = lane >> 2, tid = lane & 3;
    uint2* dst = ((uint2*)g_wf) + ((size_t)blockIdx.x)*1024;
    const int h = j*8 + g;
    #pragma unroll
    for (int tk = 0; tk < 4; tk++){
        const int c0 = ch*64 + tk*16 + 2*tid;
        uint2 v;
        v.x = pk(W[(size_t)(c0    )*Hh + h], W[(size_t)(c0+1)*Hh + h]);
        v.y = pk(W[(size_t)(c0 + 8)*Hh + h], W[(size_t)(c0+9)*Hh + h]);
        dst[(j*4 + tk)*32 + lane] = v;
    }
}

// ---------------------------------------------------------------------------
// proj (fused q,k,v, all-fp16 MMAs): 128 rows/CTA. Warp = (mg=w&3, whh=w>>2):
// m32 x 12 j-tiles over flattened [K(8) | Q(8) | V(8)].
// ---------------------------------------------------------------------------
#define PJ_STAGE 61440
#define PJ_XS(s)      ((s)*PJ_STAGE)
#define PJ_WB(s, wh)  ((s)*PJ_STAGE + 36864 + (wh)*8192)
#define PROJ_SMEM (2*PJ_STAGE)

__global__ void __launch_bounds__(256) proj_tc(const float* __restrict__ x)
{
    extern __shared__ __align__(16) char sm[];
    const uint32_t sb = smem_u32(sm);
    const int t = threadIdx.x, w = t>>5, lane = t&31, g = lane>>2, tid = lane&3;
    const int mg = w & 3, whh = w >> 2;
    const int B = blockIdx.x;
    const int row0 = B * 128;

    const float4* wsrc = (const float4*)g_wf;   // 512 float4 per (which,chunk)

    #define PJ_COPY(ch, s) do{                                               \
        uint32_t xd = sb + PJ_XS(s);                                          \
        _Pragma("unroll")                                                     \
        for (int i_ = 0; i_ < 8; i_++){                                       \
            int idx_ = t + 256*i_;                                            \
            int r_ = idx_ >> 4, c4_ = idx_ & 15;                              \
            CP16(xd + r_*288 + c4_*16,                                        \
                 x + (size_t)(row0 + r_)*Cc + (ch)*64 + c4_*4);               \
        }                                                                     \
        _Pragma("unroll")                                                     \
        for (int wh_ = 0; wh_ < 3; wh_++){                                    \
            uint32_t wd = sb + PJ_WB(s, wh_);                                 \
            const float4* ws = wsrc + wh_*6144 + (ch)*512;                    \
            _Pragma("unroll")                                                 \
            for (int i_ = 0; i_ < 2; i_++) CP16(wd + (t+256*i_)*16, ws + t + 256*i_); \
        }                                                                     \
        CP_COMMIT();                                                          \
    } while(0)

    float oC[2][12][4];
    #pragma unroll
    for (int mi = 0; mi < 2; mi++)
        #pragma unroll
        for (int lj = 0; lj < 12; lj++){
            oC[mi][lj][0]=oC[mi][lj][1]=oC[mi][lj][2]=oC[mi][lj][3]=0.f;
        }

    PJ_COPY(0, 0);
    PJ_COPY(1, 1);

    const int ra = 32*mg + g;

    for (int ch = 0; ch < 12; ch++){
        if (ch < 11) { CP_WAIT(1); } else { CP_WAIT(0); }
        __syncthreads();
        const int s = ch & 1;
        const float* xs = (const float*)(sm + PJ_XS(s));
        #pragma unroll
        for (int tk = 0; tk < 4; tk++){
            const int k0 = 16*tk + 2*tid;
            float2 x00 = *(const float2*)&xs[(ra     )*72 + k0    ];
            float2 x80 = *(const float2*)&xs[(ra +  8)*72 + k0    ];
            float2 x01 = *(const float2*)&xs[(ra     )*72 + k0 + 8];
            float2 x81 = *(const float2*)&xs[(ra +  8)*72 + k0 + 8];
            float2 y00 = *(const float2*)&xs[(ra + 16)*72 + k0    ];
            float2 y80 = *(const float2*)&xs[(ra + 24)*72 + k0    ];
            float2 y01 = *(const float2*)&xs[(ra + 16)*72 + k0 + 8];
            float2 y81 = *(const float2*)&xs[(ra + 24)*72 + k0 + 8];
            const uint32_t A00 = pk(x00.x, x00.y), A01 = pk(x80.x, x80.y);
            const uint32_t A02 = pk(x01.x, x01.y), A03 = pk(x81.x, x81.y);
            const uint32_t A10 = pk(y00.x, y00.y), A11 = pk(y80.x, y80.y);
            const uint32_t A12 = pk(y01.x, y01.y), A13 = pk(y81.x, y81.y);
            #pragma unroll
            for (int lj = 0; lj < 12; lj++){
                const int jt = 12*whh + lj;
                const int wh = jt >> 3, j = jt & 7;
                uint2 Bf = *(const uint2*)(sm + PJ_WB(s, wh) + (((j*4+tk)*32 + lane)<<3));
                mma16(oC[0][lj], A00, A01, A02, A03, Bf);
                mma16(oC[1][lj], A10, A11, A12, A13, Bf);
            }
        }
        __syncthreads();
        if (ch + 2 < 12) PJ_COPY(ch+2, s);
    }

    // ---- epilogue: fp16 fragment-native gmem writes ----
    const int b = B >> 4;
    const float qsc = rsqrtf((float)Cc) * 1.44269504f;
    uint32_t* qb32 = (uint32_t*)g_qf + (size_t)B*4096;   // 8192 fp16 / qblk

    #pragma unroll
    for (int mi = 0; mi < 2; mi++){
        const int mt = 2*mg + mi;
        const int ktile = 2*(B & 15) + (mt>>2);
        const size_t ktb32 = ((size_t)(b*32 + ktile))*2048;  // 4096 fp16 / ktile

        if (whh == 0){
            // K: lj 0..7 -> h-tile a; fp16 B-frag k16 (n=token, k=h)
            uint32_t* kb32 = (uint32_t*)g_kf + ktb32;
            const int jn0 = 2*(mt & 3);
            #pragma unroll
            for (int a = 0; a < 8; a++){
                const int base = ((jn0*4 + (a>>1))*32 + g*4 + tid)*2 + (a&1);
                kb32[base]       = pk(oC[mi][a][0], oC[mi][a][1]);
                kb32[base + 256] = pk(oC[mi][a][2], oC[mi][a][3]);
            }
            // Q: lj 8..11 -> ja 0..3; fp16 A-frag k16
            #pragma unroll
            for (int a = 0; a < 4; a++){
                const int ja = a;
                const int Wq = ((mt*4 + (ja>>1))*32 + g*4 + tid)*4 + 2*(ja&1);
                qb32[Wq]   = pk(qsc*oC[mi][8+a][0], qsc*oC[mi][8+a][1]);
                qb32[Wq+1] = pk(qsc*oC[mi][8+a][2], qsc*oC[mi][8+a][3]);
            }
        } else {
            // Q: lj 0..3 -> ja 4..7
            #pragma unroll
            for (int a = 0; a < 4; a++){
                const int ja = 4 + a;
                const int Wq = ((mt*4 + (ja>>1))*32 + g*4 + tid)*4 + 2*(ja&1);
                qb32[Wq]   = pk(qsc*oC[mi][a][0], qsc*oC[mi][a][1]);
                qb32[Wq+1] = pk(qsc*oC[mi][a][2], qsc*oC[mi][a][3]);
            }
            // V: lj 4..11 -> h-tile a; fp16 B-frag k16 (n=h, k=token)
            __half* vb = (__half*)g_vf + ktb32*2;
            #pragma unroll
            for (int a = 0; a < 8; a++){
                const int i0 = (((a*4 + (mt&3))*32 + 8*tid + (g>>1))*2)*2 + (g&1);
                vb[i0]      = __float2half(oC[mi][4+a][0]);
                vb[i0 + 16] = __float2half(oC[mi][4+a][1]);
                vb[i0 + 2]  = __float2half(oC[mi][4+a][2]);
                vb[i0 + 18] = __float2half(oC[mi][4+a][3]);
            }
        }
    }
}

// ---------------------------------------------------------------------------
// Attention (fp16 k16, triple-buffered K/V, ONE sync per tile, fused
// finalize): 128 q rows x 1024 keys per CTA (kh split over blockIdx.z).
// The last-finishing CTA of each (b,qblk) pair combines both partials
// (own in registers, other via L2) and writes the final output.
// ---------------------------------------------------------------------------
#define AOSM   0                    // Q (16KB); Osm (33792B) overlay at epilogue
#define AKB(s) (16384 + (s)*8192)   // 3 K stages
#define AVB(s) (40960 + (s)*8192)   // 3 V stages
#define ALSM   65536
#define ATTN_SMEM 66064
#define NKT 16

__global__ void __launch_bounds__(256, 2) attn_tc(float* __restrict__ out)
{
    extern __shared__ __align__(16) char sm[];
    const uint32_t sb = smem_u32(sm);
    const int t = threadIdx.x, w = t>>5, lane = t&31, g = lane>>2, tid = lane&3;
    const int mg = w & 3, nh = w >> 2;
    const int qblk = blockIdx.x, b = blockIdx.y, kh = blockIdx.z;

    const float4* qsrc  = ((const float4*)g_qf) + ((size_t)(b*16 + qblk))*1024;
    const float4* kbase = ((const float4*)g_kf) + (size_t)b*16384 + (size_t)kh*NKT*512;
    const float4* vbase = ((const float4*)g_vf) + (size_t)b*16384 + (size_t)kh*NKT*512;

    #define KV_COPY(tile, s) do{                                             \
        uint32_t kd = sb + AKB(s);                                           \
        uint32_t vd = sb + AVB(s);                                           \
        const float4* ks = kbase + (tile)*512;                               \
        const float4* vs = vbase + (tile)*512;                               \
        _Pragma("unroll")                                                    \
        for (int i_ = 0; i_ < 2; i_++) CP16(kd + (t+256*i_)*16, ks + t + 256*i_); \
        _Pragma("unroll")                                                    \
        for (int i_ = 0; i_ < 2; i_++) CP16(vd + (t+256*i_)*16, vs + t + 256*i_); \
        CP_COMMIT();                                                         \
    } while(0)

    // prologue: {Q + KV tile0} as group 0, KV tile1 as group 1
    {
        #pragma unroll
        for (int i = 0; i < 4; i++)
            CP16(sb + AOSM + (t+256*i)*16, qsrc + t + 256*i);
        uint32_t kd = sb + AKB(0), vd = sb + AVB(0);
        #pragma unroll
        for (int i = 0; i < 2; i++){
            CP16(kd + (t+256*i)*16, kbase + t + 256*i);
            CP16(vd + (t+256*i)*16, vbase + t + 256*i);
        }
        CP_COMMIT();
        KV_COPY(1, 1);
    }

    float o0[8][4], o1[8][4];
    #pragma unroll
    for (int j = 0; j < 8; j++){
        o0[j][0]=o0[j][1]=o0[j][2]=o0[j][3]=0.f;
        o1[j][0]=o1[j][1]=o1[j][2]=o1[j][3]=0.f;
    }
    float lsA = 0.f, lsB = 0.f, lsC = 0.f, lsD = 0.f;

    for (int it = 0; it < NKT; it++){
        if (it < NKT-1) { CP_WAIT(1); } else { CP_WAIT(0); }
        __syncthreads();
        // refill the stage retired at it-1 (all warps passed it before this sync)
        if (it + 2 < NKT) KV_COPY(it+2, (it+2)%3);
        const int s = it % 3;
        const uint32_t kbo = AKB(s);
        const uint32_t vbo = AVB(s);

        // ---- S = Q @ K^T : fp16 k16, 4 k-steps over 64 dims ----
        float s0[4][4], s1[4][4];
        #pragma unroll
        for (int j = 0; j < 4; j++){
            s0[j][0]=s0[j][1]=s0[j][2]=s0[j][3]=0.f;
            s1[j][0]=s1[j][1]=s1[j][2]=s1[j][3]=0.f;
        }
        #pragma unroll
        for (int tk = 0; tk < 4; tk++){
            uint4 A0 = *(const uint4*)(sm + AOSM + ((((2*mg  )*4+tk)*32 + lane)<<4));
            uint4 A1 = *(const uint4*)(sm + AOSM + ((((2*mg+1)*4+tk)*32 + lane)<<4));
            #pragma unroll
            for (int j = 0; j < 4; j++){
                uint2 Bf = *(const uint2*)(sm + kbo + ((((4*nh+j)*4+tk)*32 + lane)<<3));
                mma16(s0[j], A0.x, A0.y, A0.z, A0.w, Bf);
                mma16(s1[j], A1.x, A1.y, A1.z, A1.w, Bf);
            }
        }

        // ---- P = exp2(S) (scale folded into Q) + row-sum partials ----
        #pragma unroll
        for (int j = 0; j < 4; j++){
            #pragma unroll
            for (int e = 0; e < 4; e++){
                s0[j][e] = exp2_mufu(s0[j][e]);
                s1[j][e] = exp2_mufu(s1[j][e]);
            }
            lsA += s0[j][0] + s0[j][1];
            lsB += s0[j][2] + s0[j][3];
            lsC += s1[j][0] + s1[j][1];
            lsD += s1[j][2] + s1[j][3];
        }

        // ---- O += P @ V : pack C-frag pairs into fp16 A-frags ----
        #pragma unroll
        for (int uw = 0; uw < 2; uw++){
            const int u = 2*nh + uw;
            const uint32_t p00 = pk(s0[2*uw  ][0], s0[2*uw  ][1]);
            const uint32_t p01 = pk(s0[2*uw  ][2], s0[2*uw  ][3]);
            const uint32_t p02 = pk(s0[2*uw+1][0], s0[2*uw+1][1]);
            const uint32_t p03 = pk(s0[2*uw+1][2], s0[2*uw+1][3]);
            const uint32_t p10 = pk(s1[2*uw  ][0], s1[2*uw  ][1]);
            const uint32_t p11 = pk(s1[2*uw  ][2], s1[2*uw  ][3]);
            const uint32_t p12 = pk(s1[2*uw+1][0], s1[2*uw+1][1]);
            const uint32_t p13 = pk(s1[2*uw+1][2], s1[2*uw+1][3]);
            #pragma unroll
            for (int jv = 0; jv < 8; jv++){
                uint2 Bf = *(const uint2*)(sm + vbo + (((jv*4 + u)*32 + lane)<<3));
                mma16(o0[jv], p00, p01, p02, p03, Bf);
                mma16(o1[jv], p10, p11, p12, p13, Bf);
            }
        }
    }

    // ---- combine nh halves within CTA ----
    lsA += __shfl_xor_sync(0xffffffffu, lsA, 1);
    lsA += __shfl_xor_sync(0xffffffffu, lsA, 2);
    lsB += __shfl_xor_sync(0xffffffffu, lsB, 1);
    lsB += __shfl_xor_sync(0xffffffffu, lsB, 2);
    lsC += __shfl_xor_sync(0xffffffffu, lsC, 1);
    lsC += __shfl_xor_sync(0xffffffffu, lsC, 2);
    lsD += __shfl_xor_sync(0xffffffffu, lsD, 1);
    lsD += __shfl_xor_sync(0xffffffffu, lsD, 2);

    float* Osm = (float*)(sm + AOSM);
    float* Lsm = (float*)(sm + ALSM);
    unsigned* Tks = (unsigned*)(sm + ALSM + 512);
    const int r0 = 32*mg + g;
    const int bq = b*16 + qblk;

    __syncthreads();
    if (nh == 1){
        #pragma unroll
        for (int jv = 0; jv < 8; jv++){
            const int c0 = 8*jv + 2*tid;
            *(float2*)&Osm[(r0     )*66 + c0] = make_float2(o0[jv][0], o0[jv][1]);
            *(float2*)&Osm[(r0 +  8)*66 + c0] = make_float2(o0[jv][2], o0[jv][3]);
            *(float2*)&Osm[(r0 + 16)*66 + c0] = make_float2(o1[jv][0], o1[jv][1]);
            *(float2*)&Osm[(r0 + 24)*66 + c0] = make_float2(o1[jv][2], o1[jv][3]);
        }
        if (tid == 0){
            Lsm[r0]      = lsA;
            Lsm[r0 + 8]  = lsB;
            Lsm[r0 + 16] = lsC;
            Lsm[r0 + 24] = lsD;
        }
    }
    __syncthreads();

    // nh==0 warps: merge nh halves into registers, write CTA partial
    float lT0 = 0.f, lT1 = 0.f, lT2 = 0.f, lT3 = 0.f;
    if (nh == 0){
        lT0 = lsA + Lsm[r0];
        lT1 = lsB + Lsm[r0 + 8];
        lT2 = lsC + Lsm[r0 + 16];
        lT3 = lsD + Lsm[r0 + 24];
        float* ob = g_op + ((size_t)kh*NROW + (size_t)b*Tt + qblk*128)*Hh;
        #pragma unroll
        for (int jv = 0; jv < 8; jv++){
            const int c0 = 8*jv + 2*tid;
            float2 a0 = *(float2*)&Osm[(r0     )*66 + c0];
            float2 a1 = *(float2*)&Osm[(r0 +  8)*66 + c0];
            float2 a2 = *(float2*)&Osm[(r0 + 16)*66 + c0];
            float2 a3 = *(float2*)&Osm[(r0 + 24)*66 + c0];
            o0[jv][0] += a0.x;  o0[jv][1] += a0.y;
            o0[jv][2] += a1.x;  o0[jv][3] += a1.y;
            o1[jv][0] += a2.x;  o1[jv][1] += a2.y;
            o1[jv][2] += a3.x;  o1[jv][3] += a3.y;
            *(float2*)&ob[(size_t)(r0     )*Hh + c0] = make_float2(o0[jv][0], o0[jv][1]);
            *(float2*)&ob[(size_t)(r0 +  8)*Hh + c0] = make_float2(o0[jv][2], o0[jv][3]);
            *(float2*)&ob[(size_t)(r0 + 16)*Hh + c0] = make_float2(o1[jv][0], o1[jv][1]);
            *(float2*)&ob[(size_t)(r0 + 24)*Hh + c0] = make_float2(o1[jv][2], o1[jv][3]);
        }
        if (tid == 0){
            float* lb = g_ls + (size_t)kh*NROW + (size_t)b*Tt + qblk*128;
            lb[r0]      = lT0;
            lb[r0 + 8]  = lT1;
            lb[r0 + 16] = lT2;
            lb[r0 + 24] = lT3;
        }
    }

    // ---- ticket: last CTA of the (b,qblk) pair finalizes ----
    __threadfence();
    __syncthreads();
    if (t == 0) Tks[0] = atomicAdd(&g_cnt[bq], 1u);
    __syncthreads();
    if (Tks[0] == 1u){
        __threadfence();   // acquire other CTA's partial
        if (nh == 0){
            const float* oo = g_op + ((size_t)(1-kh)*NROW + (size_t)b*Tt + qblk*128)*Hh;
            const float* lo = g_ls + (size_t)(1-kh)*NROW + (size_t)b*Tt + qblk*128;
            const float iA = 1.f / (lT0 + __ldcg(&lo[r0]));
            const float iB = 1.f / (lT1 + __ldcg(&lo[r0 + 8]));
            const float iC = 1.f / (lT2 + __ldcg(&lo[r0 + 16]));
            const float iD = 1.f / (lT3 + __ldcg(&lo[r0 + 24]));
            float* ob = out + ((size_t)b*Tt + qblk*128)*Hh;
            #pragma unroll
            for (int jv = 0; jv < 8; jv++){
                const int c0 = 8*jv + 2*tid;
                float2 b0 = __ldcg((const float2*)&oo[(size_t)(r0     )*Hh + c0]);
                float2 b1 = __ldcg((const float2*)&oo[(size_t)(r0 +  8)*Hh + c0]);
                float2 b2 = __ldcg((const float2*)&oo[(size_t)(r0 + 16)*Hh + c0]);
                float2 b3 = __ldcg((const float2*)&oo[(size_t)(r0 + 24)*Hh + c0]);
                *(float2*)&ob[(size_t)(r0     )*Hh + c0] =
                    make_float2((o0[jv][0]+b0.x)*iA, (o0[jv][1]+b0.y)*iA);
                *(float2*)&ob[(size_t)(r0 +  8)*Hh + c0] =
                    make_float2((o0[jv][2]+b1.x)*iB, (o0[jv][3]+b1.y)*iB);
                *(float2*)&ob[(size_t)(r0 + 16)*Hh + c0] =
                    make_float2((o1[jv][0]+b2.x)*iC, (o1[jv][1]+b2.y)*iC);
                *(float2*)&ob[(size_t)(r0 + 24)*Hh + c0] =
                    make_float2((o1[jv][2]+b3.x)*iD, (o1[jv][3]+b3.y)*iD);
            }
        }
        if (t == 0) g_cnt[bq] = 0u;   // reset for next graph replay
    }
}

// ---------------------------------------------------------------------------
extern "C" void kernel_launch(void* const* d_in, const int* in_sizes, int n_in,
                              void* d_out, int out_size)
{
    const float* x  = (const float*)d_in[0];
    const float* Wk = (const float*)d_in[1];
    const float* Wq = (const float*)d_in[2];
    const float* Wv = (const float*)d_in[3];
    float* out = (float*)d_out;

    cudaFuncSetAttribute(proj_tc, cudaFuncAttributeMaxDynamicSharedMemorySize, PROJ_SMEM);
    cudaFuncSetAttribute(attn_tc, cudaFuncAttributeMaxDynamicSharedMemorySize, ATTN_SMEM);

    prep_w<<<36, 256>>>(Wk, Wq, Wv);
    proj_tc<<<128, 256, PROJ_SMEM>>>(x);
    attn_tc<<<dim3(16, 8, 2), 256, ATTN_SMEM>>>(out);
}